// round 14
// baseline (speedup 1.0000x reference)
#include <cuda_runtime.h>
#include <math.h>

// Problem constants (fixed by reference: N_NODES=10000, N_EDGES=160000, H=128, L=16)
#define H      128
#define NMAX   10000
#define LAYERS 16
#define EPSV   1e-5f
#define ET     8   // edges per block
#define NT     8   // nodes per block

// Scratch: per-layer scatter-sum accumulator (no cudaMalloc allowed)
__device__ float g_agg[(size_t)NMAX * H];

__global__ void zero_agg_kernel(int total) {
    int i = blockIdx.x * blockDim.x + threadIdx.x;
    if (i < total) g_agg[i] = 0.0f;
}

// acc[0..7] += w * sp[0..7]  (sp 16B-aligned shared row, broadcast)
__device__ __forceinline__ void fma8(float (&acc)[8], float w, const float* sp) {
    float4 c0 = *reinterpret_cast<const float4*>(sp);
    float4 c1 = *reinterpret_cast<const float4*>(sp + 4);
    acc[0] = fmaf(w, c0.x, acc[0]);
    acc[1] = fmaf(w, c0.y, acc[1]);
    acc[2] = fmaf(w, c0.z, acc[2]);
    acc[3] = fmaf(w, c0.w, acc[3]);
    acc[4] = fmaf(w, c1.x, acc[4]);
    acc[5] = fmaf(w, c1.y, acc[5]);
    acc[6] = fmaf(w, c1.z, acc[6]);
    acc[7] = fmaf(w, c1.w, acc[7]);
}

__device__ __forceinline__ float silu_f(float x) {
    // x * sigmoid(x); __expf fast-path is accurate to ~1e-6 rel, fine vs 1e-3 gate
    return x / (1.0f + __expf(-x));
}

// ---------------------------------------------------------------------------
// Edge update: cat=[ef, nf[src], nf[dst]] (3H) -> Lin+SiLU -> Lin -> LN -> +ef
// Also scatter-adds the new edge feature into g_agg[dst].
// One block = 8 edges, 128 threads (thread j owns output column j).
// ---------------------------------------------------------------------------
__global__ __launch_bounds__(128) void edge_kernel(
    float* __restrict__ ef, const float* __restrict__ nf,
    const int* __restrict__ src, const int* __restrict__ dst,
    const float* __restrict__ W1, const float* __restrict__ b1,   // W1: [3H][H]
    const float* __restrict__ W2, const float* __restrict__ b2,   // W2: [H][H]
    const float* __restrict__ gg, const float* __restrict__ bb)
{
    __shared__ __align__(16) float s_cat[3 * H][ET]; // transposed: [k][edge]
    __shared__ __align__(16) float s_h[H][ET];
    __shared__ float s_red[2][ET][4];

    const int tid = threadIdx.x;
    const int e0  = blockIdx.x * ET;

    int di[ET];
#pragma unroll
    for (int e = 0; e < ET; e++) {
        int ei = e0 + e;
        int si = src[ei];
        di[e]  = dst[ei];
        s_cat[tid][e]         = ef[(size_t)ei * H + tid];
        s_cat[H + tid][e]     = nf[(size_t)si * H + tid];
        s_cat[2 * H + tid][e] = nf[(size_t)di[e] * H + tid];
    }
    __syncthreads();

    // ---- GEMM1 (K=3H) + SiLU ----
    float acc[ET];
    {
        float b = b1[tid];
#pragma unroll
        for (int e = 0; e < ET; e++) acc[e] = b;
    }
    const float* w1p = W1 + tid;  // column j, coalesced across threads
#pragma unroll 4
    for (int k = 0; k < 3 * H; k++) {
        float w = w1p[(size_t)k * H];
        fma8(acc, w, &s_cat[k][0]);
    }
#pragma unroll
    for (int e = 0; e < ET; e++) s_h[tid][e] = silu_f(acc[e]);
    __syncthreads();

    // ---- GEMM2 (K=H) ----
    float acc2[ET];
    {
        float b = b2[tid];
#pragma unroll
        for (int e = 0; e < ET; e++) acc2[e] = b;
    }
    const float* w2p = W2 + tid;
#pragma unroll 4
    for (int k = 0; k < H; k++) {
        float w = w2p[(size_t)k * H];
        fma8(acc2, w, &s_h[k][0]);
    }

    // ---- LayerNorm over the 128 columns (per edge) ----
    float sum[ET], sq[ET];
#pragma unroll
    for (int e = 0; e < ET; e++) { sum[e] = acc2[e]; sq[e] = acc2[e] * acc2[e]; }
#pragma unroll
    for (int off = 16; off > 0; off >>= 1) {
#pragma unroll
        for (int e = 0; e < ET; e++) {
            sum[e] += __shfl_xor_sync(0xffffffffu, sum[e], off);
            sq[e]  += __shfl_xor_sync(0xffffffffu, sq[e],  off);
        }
    }
    const int warp = tid >> 5;
    if ((tid & 31) == 0) {
#pragma unroll
        for (int e = 0; e < ET; e++) { s_red[0][e][warp] = sum[e]; s_red[1][e][warp] = sq[e]; }
    }
    __syncthreads();

    const float gj = gg[tid], bj = bb[tid];
#pragma unroll
    for (int e = 0; e < ET; e++) {
        float s   = s_red[0][e][0] + s_red[0][e][1] + s_red[0][e][2] + s_red[0][e][3];
        float ss  = s_red[1][e][0] + s_red[1][e][1] + s_red[1][e][2] + s_red[1][e][3];
        float mu  = s * (1.0f / H);
        float var = fmaxf(ss * (1.0f / H) - mu * mu, 0.0f);
        float inv = rsqrtf(var + EPSV);
        float out = s_cat[tid][e] + (acc2[e] - mu) * inv * gj + bj;  // residual
        int ei = e0 + e;
        ef[(size_t)ei * H + tid] = out;
        atomicAdd(&g_agg[(size_t)di[e] * H + tid], out);  // segment_sum by dst
    }
}

// ---------------------------------------------------------------------------
// Node update: cat=[agg, nf] (2H) -> Lin+SiLU -> Lin -> LN -> +nf (in place)
// ---------------------------------------------------------------------------
__global__ __launch_bounds__(128) void node_kernel(
    float* __restrict__ nfio,
    const float* __restrict__ W1, const float* __restrict__ b1,   // W1: [2H][H]
    const float* __restrict__ W2, const float* __restrict__ b2,   // W2: [H][H]
    const float* __restrict__ gg, const float* __restrict__ bb)
{
    __shared__ __align__(16) float s_cat[2 * H][NT];
    __shared__ __align__(16) float s_h[H][NT];
    __shared__ float s_red[2][NT][4];

    const int tid = threadIdx.x;
    const int n0  = blockIdx.x * NT;

#pragma unroll
    for (int e = 0; e < NT; e++) {
        int ni = n0 + e;
        s_cat[tid][e]     = g_agg[(size_t)ni * H + tid];
        s_cat[H + tid][e] = nfio[(size_t)ni * H + tid];
    }
    __syncthreads();

    float acc[NT];
    {
        float b = b1[tid];
#pragma unroll
        for (int e = 0; e < NT; e++) acc[e] = b;
    }
    const float* w1p = W1 + tid;
#pragma unroll 4
    for (int k = 0; k < 2 * H; k++) {
        float w = w1p[(size_t)k * H];
        fma8(acc, w, &s_cat[k][0]);
    }
#pragma unroll
    for (int e = 0; e < NT; e++) s_h[tid][e] = silu_f(acc[e]);
    __syncthreads();

    float acc2[NT];
    {
        float b = b2[tid];
#pragma unroll
        for (int e = 0; e < NT; e++) acc2[e] = b;
    }
    const float* w2p = W2 + tid;
#pragma unroll 4
    for (int k = 0; k < H; k++) {
        float w = w2p[(size_t)k * H];
        fma8(acc2, w, &s_h[k][0]);
    }

    float sum[NT], sq[NT];
#pragma unroll
    for (int e = 0; e < NT; e++) { sum[e] = acc2[e]; sq[e] = acc2[e] * acc2[e]; }
#pragma unroll
    for (int off = 16; off > 0; off >>= 1) {
#pragma unroll
        for (int e = 0; e < NT; e++) {
            sum[e] += __shfl_xor_sync(0xffffffffu, sum[e], off);
            sq[e]  += __shfl_xor_sync(0xffffffffu, sq[e],  off);
        }
    }
    const int warp = tid >> 5;
    if ((tid & 31) == 0) {
#pragma unroll
        for (int e = 0; e < NT; e++) { s_red[0][e][warp] = sum[e]; s_red[1][e][warp] = sq[e]; }
    }
    __syncthreads();

    const float gj = gg[tid], bj = bb[tid];
#pragma unroll
    for (int e = 0; e < NT; e++) {
        float s   = s_red[0][e][0] + s_red[0][e][1] + s_red[0][e][2] + s_red[0][e][3];
        float ss  = s_red[1][e][0] + s_red[1][e][1] + s_red[1][e][2] + s_red[1][e][3];
        float mu  = s * (1.0f / H);
        float var = fmaxf(ss * (1.0f / H) - mu * mu, 0.0f);
        float inv = rsqrtf(var + EPSV);
        float out = s_cat[H + tid][e] + (acc2[e] - mu) * inv * gj + bj; // residual
        nfio[(size_t)(n0 + e) * H + tid] = out;
    }
}

extern "C" void kernel_launch(void* const* d_in, const int* in_sizes, int n_in,
                              void* d_out, int out_size)
{
    const float* efeat = (const float*)d_in[0];
    const float* nfeat = (const float*)d_in[1];
    const int*   src   = (const int*)  d_in[2];
    const int*   dst   = (const int*)  d_in[3];
    const float* eW1   = (const float*)d_in[4];
    const float* eb1   = (const float*)d_in[5];
    const float* eW2   = (const float*)d_in[6];
    const float* eb2   = (const float*)d_in[7];
    const float* eg    = (const float*)d_in[8];
    const float* ebt   = (const float*)d_in[9];
    const float* nW1   = (const float*)d_in[10];
    const float* nb1   = (const float*)d_in[11];
    const float* nW2   = (const float*)d_in[12];
    const float* nb2   = (const float*)d_in[13];
    const float* ng    = (const float*)d_in[14];
    const float* nbt   = (const float*)d_in[15];

    const int E = in_sizes[0] / H;   // 160000
    const int N = in_sizes[1] / H;   // 10000

    // Output layout: ef [E*H] then nf [N*H]; operate in place on d_out.
    float* ef = (float*)d_out;
    float* nf = ef + (size_t)E * H;

    cudaMemcpyAsync(ef, efeat, sizeof(float) * (size_t)E * H, cudaMemcpyDeviceToDevice);
    cudaMemcpyAsync(nf, nfeat, sizeof(float) * (size_t)N * H, cudaMemcpyDeviceToDevice);

    const int aggTotal = N * H;
    for (int l = 0; l < LAYERS; l++) {
        zero_agg_kernel<<<(aggTotal + 255) / 256, 256>>>(aggTotal);
        edge_kernel<<<E / ET, 128>>>(
            ef, nf, src, dst,
            eW1 + (size_t)l * 3 * H * H, eb1 + (size_t)l * H,
            eW2 + (size_t)l * H * H,     eb2 + (size_t)l * H,
            eg  + (size_t)l * H,         ebt + (size_t)l * H);
        node_kernel<<<N / NT, 128>>>(
            nf,
            nW1 + (size_t)l * 2 * H * H, nb1 + (size_t)l * H,
            nW2 + (size_t)l * H * H,     nb2 + (size_t)l * H,
            ng  + (size_t)l * H,         nbt + (size_t)l * H);
    }
}

// round 15
// speedup vs baseline: 1.1022x; 1.1022x over previous
#include <cuda_runtime.h>
#include <math.h>

// Problem constants (fixed: N_NODES=10000, N_EDGES=160000, H=128, L=16)
#define H      128
#define NMAX   10000
#define LAYERS 16
#define EPSV   1e-5f
#define ET     16   // edges per block
#define NT     16   // nodes per block
#define PADR   20   // padded shared row length (floats): 80B, 16B-aligned, 4-way-conflict stores

// Scratch: per-layer scatter-sum accumulator (no cudaMalloc allowed)
__device__ float g_agg[(size_t)NMAX * H];

__global__ void zero_agg_kernel(int total) {
    int i = blockIdx.x * blockDim.x + threadIdx.x;
    if (i < total) g_agg[i] = 0.0f;
}

// ---- packed f32x2 helpers (FFMA2 — 2x fp32 FMA throughput on sm_103a) ----
__device__ __forceinline__ void ffma2(unsigned long long& d,
                                      unsigned long long a,
                                      unsigned long long b) {
    asm("fma.rn.f32x2 %0, %1, %2, %0;" : "+l"(d) : "l"(a), "l"(b));
}
__device__ __forceinline__ unsigned long long pack2(float x, float y) {
    unsigned long long r;
    asm("mov.b64 %0, {%1, %2};" : "=l"(r) : "f"(x), "f"(y));
    return r;
}
__device__ __forceinline__ float2 unpack2(unsigned long long v) {
    float2 r;
    asm("mov.b64 {%0, %1}, %2;" : "=f"(r.x), "=f"(r.y) : "l"(v));
    return r;
}

__device__ __forceinline__ float silu_f(float x) {
    return x / (1.0f + __expf(-x));
}

// One k-step: acc pairs {0..7} += {w,w} * s_row[0..15]; s_row is a broadcast
// 80B-aligned shared row (4x LDS.128).
__device__ __forceinline__ void fma16_row(unsigned long long (&acc)[8],
                                          unsigned long long ww,
                                          const float* s_row) {
    const ulonglong2* cp = reinterpret_cast<const ulonglong2*>(s_row);
    ulonglong2 c0 = cp[0];
    ulonglong2 c1 = cp[1];
    ulonglong2 c2 = cp[2];
    ulonglong2 c3 = cp[3];
    ffma2(acc[0], ww, c0.x); ffma2(acc[1], ww, c0.y);
    ffma2(acc[2], ww, c1.x); ffma2(acc[3], ww, c1.y);
    ffma2(acc[4], ww, c2.x); ffma2(acc[5], ww, c2.y);
    ffma2(acc[6], ww, c3.x); ffma2(acc[7], ww, c3.y);
}

// ---------------------------------------------------------------------------
// Edge update: cat=[ef, nf[src], nf[dst]] (3H) -> Lin+SiLU -> Lin -> LN -> +ef
// Also scatter-adds the new edge feature into g_agg[dst].
// One block = 16 edges, 128 threads (thread j owns output column j).
// ---------------------------------------------------------------------------
__global__ __launch_bounds__(128) void edge_kernel(
    float* __restrict__ ef, const float* __restrict__ nf,
    const int* __restrict__ src, const int* __restrict__ dst,
    const float* __restrict__ W1, const float* __restrict__ b1,   // W1: [3H][H]
    const float* __restrict__ W2, const float* __restrict__ b2,   // W2: [H][H]
    const float* __restrict__ gg, const float* __restrict__ bb)
{
    __shared__ __align__(16) float s_cat[3 * H][PADR]; // transposed: [k][edge]
    __shared__ __align__(16) float s_h[H][PADR];
    __shared__ float s_red[2][ET][4];

    const int tid = threadIdx.x;
    const int e0  = blockIdx.x * ET;

#pragma unroll
    for (int e = 0; e < ET; e++) {
        int ei = e0 + e;
        int si = __ldg(&src[ei]);
        int di = __ldg(&dst[ei]);
        s_cat[tid][e]         = ef[(size_t)ei * H + tid];
        s_cat[H + tid][e]     = nf[(size_t)si * H + tid];
        s_cat[2 * H + tid][e] = nf[(size_t)di * H + tid];
    }
    __syncthreads();

    // ---- GEMM1 (K=3H) + SiLU ----
    unsigned long long acc[8];
    {
        float b = b1[tid];
        unsigned long long bbp = pack2(b, b);
#pragma unroll
        for (int i = 0; i < 8; i++) acc[i] = bbp;
    }
    const float* w1p = W1 + tid;  // column j; coalesced across threads
#pragma unroll 4
    for (int k = 0; k < 3 * H; k++) {
        float w = w1p[(size_t)k * H];
        fma16_row(acc, pack2(w, w), &s_cat[k][0]);
    }
    {
        float4 hv[4];
#pragma unroll
        for (int i = 0; i < 8; i++) {
            float2 p = unpack2(acc[i]);
            reinterpret_cast<float2*>(hv)[i] = make_float2(silu_f(p.x), silu_f(p.y));
        }
        float4* hrow = reinterpret_cast<float4*>(&s_h[tid][0]);
#pragma unroll
        for (int i = 0; i < 4; i++) hrow[i] = hv[i];
    }
    __syncthreads();

    // ---- GEMM2 (K=H) ----
    unsigned long long acc2[8];
    {
        float b = b2[tid];
        unsigned long long bbp = pack2(b, b);
#pragma unroll
        for (int i = 0; i < 8; i++) acc2[i] = bbp;
    }
    const float* w2p = W2 + tid;
#pragma unroll 4
    for (int k = 0; k < H; k++) {
        float w = w2p[(size_t)k * H];
        fma16_row(acc2, pack2(w, w), &s_h[k][0]);
    }

    // ---- LayerNorm over the 128 columns (per edge) ----
    float vals[ET], sum[ET], sq[ET];
#pragma unroll
    for (int i = 0; i < 8; i++) {
        float2 p = unpack2(acc2[i]);
        vals[2 * i] = p.x; vals[2 * i + 1] = p.y;
    }
#pragma unroll
    for (int e = 0; e < ET; e++) { sum[e] = vals[e]; sq[e] = vals[e] * vals[e]; }
#pragma unroll
    for (int off = 16; off > 0; off >>= 1) {
#pragma unroll
        for (int e = 0; e < ET; e++) {
            sum[e] += __shfl_xor_sync(0xffffffffu, sum[e], off);
            sq[e]  += __shfl_xor_sync(0xffffffffu, sq[e],  off);
        }
    }
    const int warp = tid >> 5;
    if ((tid & 31) == 0) {
#pragma unroll
        for (int e = 0; e < ET; e++) { s_red[0][e][warp] = sum[e]; s_red[1][e][warp] = sq[e]; }
    }
    __syncthreads();

    const float gj = gg[tid], bj = bb[tid];
#pragma unroll
    for (int e = 0; e < ET; e++) {
        float s   = s_red[0][e][0] + s_red[0][e][1] + s_red[0][e][2] + s_red[0][e][3];
        float ss  = s_red[1][e][0] + s_red[1][e][1] + s_red[1][e][2] + s_red[1][e][3];
        float mu  = s * (1.0f / H);
        float var = fmaxf(ss * (1.0f / H) - mu * mu, 0.0f);
        float inv = rsqrtf(var + EPSV);
        float out = s_cat[tid][e] + (vals[e] - mu) * inv * gj + bj;  // residual
        int ei = e0 + e;
        int di = __ldg(&dst[ei]);
        ef[(size_t)ei * H + tid] = out;
        atomicAdd(&g_agg[(size_t)di * H + tid], out);  // segment_sum by dst
    }
}

// ---------------------------------------------------------------------------
// Node update: cat=[agg, nf] (2H) -> Lin+SiLU -> Lin -> LN -> +nf (in place)
// ---------------------------------------------------------------------------
__global__ __launch_bounds__(128) void node_kernel(
    float* __restrict__ nfio,
    const float* __restrict__ W1, const float* __restrict__ b1,   // W1: [2H][H]
    const float* __restrict__ W2, const float* __restrict__ b2,   // W2: [H][H]
    const float* __restrict__ gg, const float* __restrict__ bb)
{
    __shared__ __align__(16) float s_cat[2 * H][PADR];
    __shared__ __align__(16) float s_h[H][PADR];
    __shared__ float s_red[2][NT][4];

    const int tid = threadIdx.x;
    const int n0  = blockIdx.x * NT;

#pragma unroll
    for (int e = 0; e < NT; e++) {
        int ni = n0 + e;
        s_cat[tid][e]     = g_agg[(size_t)ni * H + tid];
        s_cat[H + tid][e] = nfio[(size_t)ni * H + tid];
    }
    __syncthreads();

    unsigned long long acc[8];
    {
        float b = b1[tid];
        unsigned long long bbp = pack2(b, b);
#pragma unroll
        for (int i = 0; i < 8; i++) acc[i] = bbp;
    }
    const float* w1p = W1 + tid;
#pragma unroll 4
    for (int k = 0; k < 2 * H; k++) {
        float w = w1p[(size_t)k * H];
        fma16_row(acc, pack2(w, w), &s_cat[k][0]);
    }
    {
        float4 hv[4];
#pragma unroll
        for (int i = 0; i < 8; i++) {
            float2 p = unpack2(acc[i]);
            reinterpret_cast<float2*>(hv)[i] = make_float2(silu_f(p.x), silu_f(p.y));
        }
        float4* hrow = reinterpret_cast<float4*>(&s_h[tid][0]);
#pragma unroll
        for (int i = 0; i < 4; i++) hrow[i] = hv[i];
    }
    __syncthreads();

    unsigned long long acc2[8];
    {
        float b = b2[tid];
        unsigned long long bbp = pack2(b, b);
#pragma unroll
        for (int i = 0; i < 8; i++) acc2[i] = bbp;
    }
    const float* w2p = W2 + tid;
#pragma unroll 4
    for (int k = 0; k < H; k++) {
        float w = w2p[(size_t)k * H];
        fma16_row(acc2, pack2(w, w), &s_h[k][0]);
    }

    float vals[NT], sum[NT], sq[NT];
#pragma unroll
    for (int i = 0; i < 8; i++) {
        float2 p = unpack2(acc2[i]);
        vals[2 * i] = p.x; vals[2 * i + 1] = p.y;
    }
#pragma unroll
    for (int e = 0; e < NT; e++) { sum[e] = vals[e]; sq[e] = vals[e] * vals[e]; }
#pragma unroll
    for (int off = 16; off > 0; off >>= 1) {
#pragma unroll
        for (int e = 0; e < NT; e++) {
            sum[e] += __shfl_xor_sync(0xffffffffu, sum[e], off);
            sq[e]  += __shfl_xor_sync(0xffffffffu, sq[e],  off);
        }
    }
    const int warp = tid >> 5;
    if ((tid & 31) == 0) {
#pragma unroll
        for (int e = 0; e < NT; e++) { s_red[0][e][warp] = sum[e]; s_red[1][e][warp] = sq[e]; }
    }
    __syncthreads();

    const float gj = gg[tid], bj = bb[tid];
#pragma unroll
    for (int e = 0; e < NT; e++) {
        float s   = s_red[0][e][0] + s_red[0][e][1] + s_red[0][e][2] + s_red[0][e][3];
        float ss  = s_red[1][e][0] + s_red[1][e][1] + s_red[1][e][2] + s_red[1][e][3];
        float mu  = s * (1.0f / H);
        float var = fmaxf(ss * (1.0f / H) - mu * mu, 0.0f);
        float inv = rsqrtf(var + EPSV);
        float out = s_cat[H + tid][e] + (vals[e] - mu) * inv * gj + bj; // residual
        nfio[(size_t)(n0 + e) * H + tid] = out;
    }
}

extern "C" void kernel_launch(void* const* d_in, const int* in_sizes, int n_in,
                              void* d_out, int out_size)
{
    const float* efeat = (const float*)d_in[0];
    const float* nfeat = (const float*)d_in[1];
    const int*   src   = (const int*)  d_in[2];
    const int*   dst   = (const int*)  d_in[3];
    const float* eW1   = (const float*)d_in[4];
    const float* eb1   = (const float*)d_in[5];
    const float* eW2   = (const float*)d_in[6];
    const float* eb2   = (const float*)d_in[7];
    const float* eg    = (const float*)d_in[8];
    const float* ebt   = (const float*)d_in[9];
    const float* nW1   = (const float*)d_in[10];
    const float* nb1   = (const float*)d_in[11];
    const float* nW2   = (const float*)d_in[12];
    const float* nb2   = (const float*)d_in[13];
    const float* ng    = (const float*)d_in[14];
    const float* nbt   = (const float*)d_in[15];

    const int E = in_sizes[0] / H;   // 160000
    const int N = in_sizes[1] / H;   // 10000

    // Output layout: ef [E*H] then nf [N*H]; operate in place on d_out.
    float* ef = (float*)d_out;
    float* nf = ef + (size_t)E * H;

    cudaMemcpyAsync(ef, efeat, sizeof(float) * (size_t)E * H, cudaMemcpyDeviceToDevice);
    cudaMemcpyAsync(nf, nfeat, sizeof(float) * (size_t)N * H, cudaMemcpyDeviceToDevice);

    const int aggTotal = N * H;
    for (int l = 0; l < LAYERS; l++) {
        zero_agg_kernel<<<(aggTotal + 255) / 256, 256>>>(aggTotal);
        edge_kernel<<<E / ET, 128>>>(
            ef, nf, src, dst,
            eW1 + (size_t)l * 3 * H * H, eb1 + (size_t)l * H,
            eW2 + (size_t)l * H * H,     eb2 + (size_t)l * H,
            eg  + (size_t)l * H,         ebt + (size_t)l * H);
        node_kernel<<<N / NT, 128>>>(
            nf,
            nW1 + (size_t)l * 2 * H * H, nb1 + (size_t)l * H,
            nW2 + (size_t)l * H * H,     nb2 + (size_t)l * H,
            ng  + (size_t)l * H,         nbt + (size_t)l * H);
    }
}

// round 16
// speedup vs baseline: 1.1067x; 1.0041x over previous
#include <cuda_runtime.h>
#include <math.h>

// Problem constants (fixed: N_NODES=10000, N_EDGES=160000, H=128, L=16)
#define H      128
#define NMAX   10000
#define LAYERS 16
#define EPSV   1e-5f
#define ET     16   // edges per block
#define NT     16   // nodes per block
#define PADR   20   // padded shared row length (floats): 80B, 16B-aligned, 4-way-conflict stores

// Scratch: per-layer scatter-sum accumulator (no cudaMalloc allowed)
__device__ float g_agg[(size_t)NMAX * H];

__global__ void zero_agg_kernel(int total) {
    int i = blockIdx.x * blockDim.x + threadIdx.x;
    if (i < total) g_agg[i] = 0.0f;
}

// ---- packed f32x2 helpers (FFMA2 — 2x fp32 FMA throughput on sm_103a) ----
__device__ __forceinline__ void ffma2(unsigned long long& d,
                                      unsigned long long a,
                                      unsigned long long b) {
    asm("fma.rn.f32x2 %0, %1, %2, %0;" : "+l"(d) : "l"(a), "l"(b));
}
__device__ __forceinline__ unsigned long long pack2(float x, float y) {
    unsigned long long r;
    asm("mov.b64 %0, {%1, %2};" : "=l"(r) : "f"(x), "f"(y));
    return r;
}
__device__ __forceinline__ float2 unpack2(unsigned long long v) {
    float2 r;
    asm("mov.b64 {%0, %1}, %2;" : "=f"(r.x), "=f"(r.y) : "l"(v));
    return r;
}

__device__ __forceinline__ float silu_f(float x) {
    return x / (1.0f + __expf(-x));
}

// One k-step: acc pairs {0..7} += {w,w} * s_row[0..15]; s_row is a broadcast
// 80B-aligned shared row (4x LDS.128).
__device__ __forceinline__ void fma16_row(unsigned long long (&acc)[8],
                                          unsigned long long ww,
                                          const float* s_row) {
    const ulonglong2* cp = reinterpret_cast<const ulonglong2*>(s_row);
    ulonglong2 c0 = cp[0];
    ulonglong2 c1 = cp[1];
    ulonglong2 c2 = cp[2];
    ulonglong2 c3 = cp[3];
    ffma2(acc[0], ww, c0.x); ffma2(acc[1], ww, c0.y);
    ffma2(acc[2], ww, c1.x); ffma2(acc[3], ww, c1.y);
    ffma2(acc[4], ww, c2.x); ffma2(acc[5], ww, c2.y);
    ffma2(acc[6], ww, c3.x); ffma2(acc[7], ww, c3.y);
}

// ---------------------------------------------------------------------------
// Edge update: cat=[ef, nf[src], nf[dst]] (3H) -> Lin+SiLU -> Lin -> LN -> +ef
// Also scatter-adds the new edge feature into g_agg[dst].
// One block = 16 edges, 128 threads (thread j owns output column j).
// ---------------------------------------------------------------------------
__global__ __launch_bounds__(128) void edge_kernel(
    float* __restrict__ ef, const float* __restrict__ nf,
    const int* __restrict__ src, const int* __restrict__ dst,
    const float* __restrict__ W1, const float* __restrict__ b1,   // W1: [3H][H]
    const float* __restrict__ W2, const float* __restrict__ b2,   // W2: [H][H]
    const float* __restrict__ gg, const float* __restrict__ bb)
{
    __shared__ __align__(16) float s_cat[3 * H][PADR]; // transposed: [k][edge]
    __shared__ __align__(16) float s_h[H][PADR];
    __shared__ float s_red[2][ET][4];

    const int tid = threadIdx.x;
    const int e0  = blockIdx.x * ET;

#pragma unroll
    for (int e = 0; e < ET; e++) {
        int ei = e0 + e;
        int si = __ldg(&src[ei]);
        int di = __ldg(&dst[ei]);
        s_cat[tid][e]         = ef[(size_t)ei * H + tid];
        s_cat[H + tid][e]     = nf[(size_t)si * H + tid];
        s_cat[2 * H + tid][e] = nf[(size_t)di * H + tid];
    }
    __syncthreads();

    // ---- GEMM1 (K=3H) + SiLU ----
    unsigned long long acc[8];
    {
        float b = b1[tid];
        unsigned long long bbp = pack2(b, b);
#pragma unroll
        for (int i = 0; i < 8; i++) acc[i] = bbp;
    }
    const float* w1p = W1 + tid;  // column j; coalesced across threads
#pragma unroll 4
    for (int k = 0; k < 3 * H; k++) {
        float w = w1p[(size_t)k * H];
        fma16_row(acc, pack2(w, w), &s_cat[k][0]);
    }
    {
        float4 hv[4];
#pragma unroll
        for (int i = 0; i < 8; i++) {
            float2 p = unpack2(acc[i]);
            reinterpret_cast<float2*>(hv)[i] = make_float2(silu_f(p.x), silu_f(p.y));
        }
        float4* hrow = reinterpret_cast<float4*>(&s_h[tid][0]);
#pragma unroll
        for (int i = 0; i < 4; i++) hrow[i] = hv[i];
    }
    __syncthreads();

    // ---- GEMM2 (K=H) ----
    unsigned long long acc2[8];
    {
        float b = b2[tid];
        unsigned long long bbp = pack2(b, b);
#pragma unroll
        for (int i = 0; i < 8; i++) acc2[i] = bbp;
    }
    const float* w2p = W2 + tid;
#pragma unroll 4
    for (int k = 0; k < H; k++) {
        float w = w2p[(size_t)k * H];
        fma16_row(acc2, pack2(w, w), &s_h[k][0]);
    }

    // ---- LayerNorm over the 128 columns (per edge) ----
    float vals[ET], sum[ET], sq[ET];
#pragma unroll
    for (int i = 0; i < 8; i++) {
        float2 p = unpack2(acc2[i]);
        vals[2 * i] = p.x; vals[2 * i + 1] = p.y;
    }
#pragma unroll
    for (int e = 0; e < ET; e++) { sum[e] = vals[e]; sq[e] = vals[e] * vals[e]; }
#pragma unroll
    for (int off = 16; off > 0; off >>= 1) {
#pragma unroll
        for (int e = 0; e < ET; e++) {
            sum[e] += __shfl_xor_sync(0xffffffffu, sum[e], off);
            sq[e]  += __shfl_xor_sync(0xffffffffu, sq[e],  off);
        }
    }
    const int warp = tid >> 5;
    if ((tid & 31) == 0) {
#pragma unroll
        for (int e = 0; e < ET; e++) { s_red[0][e][warp] = sum[e]; s_red[1][e][warp] = sq[e]; }
    }
    __syncthreads();

    const float gj = gg[tid], bj = bb[tid];
#pragma unroll
    for (int e = 0; e < ET; e++) {
        float s   = s_red[0][e][0] + s_red[0][e][1] + s_red[0][e][2] + s_red[0][e][3];
        float ss  = s_red[1][e][0] + s_red[1][e][1] + s_red[1][e][2] + s_red[1][e][3];
        float mu  = s * (1.0f / H);
        float var = fmaxf(ss * (1.0f / H) - mu * mu, 0.0f);
        float inv = rsqrtf(var + EPSV);
        float out = s_cat[tid][e] + (vals[e] - mu) * inv * gj + bj;  // residual
        int ei = e0 + e;
        int di = __ldg(&dst[ei]);
        ef[(size_t)ei * H + tid] = out;
        atomicAdd(&g_agg[(size_t)di * H + tid], out);  // segment_sum by dst
    }
}

// ---------------------------------------------------------------------------
// Node update: cat=[agg, nf] (2H) -> Lin+SiLU -> Lin -> LN -> +nf (in place)
// ---------------------------------------------------------------------------
__global__ __launch_bounds__(128) void node_kernel(
    float* __restrict__ nfio,
    const float* __restrict__ W1, const float* __restrict__ b1,   // W1: [2H][H]
    const float* __restrict__ W2, const float* __restrict__ b2,   // W2: [H][H]
    const float* __restrict__ gg, const float* __restrict__ bb)
{
    __shared__ __align__(16) float s_cat[2 * H][PADR];
    __shared__ __align__(16) float s_h[H][PADR];
    __shared__ float s_red[2][NT][4];

    const int tid = threadIdx.x;
    const int n0  = blockIdx.x * NT;

#pragma unroll
    for (int e = 0; e < NT; e++) {
        int ni = n0 + e;
        s_cat[tid][e]     = g_agg[(size_t)ni * H + tid];
        s_cat[H + tid][e] = nfio[(size_t)ni * H + tid];
    }
    __syncthreads();

    unsigned long long acc[8];
    {
        float b = b1[tid];
        unsigned long long bbp = pack2(b, b);
#pragma unroll
        for (int i = 0; i < 8; i++) acc[i] = bbp;
    }
    const float* w1p = W1 + tid;
#pragma unroll 4
    for (int k = 0; k < 2 * H; k++) {
        float w = w1p[(size_t)k * H];
        fma16_row(acc, pack2(w, w), &s_cat[k][0]);
    }
    {
        float4 hv[4];
#pragma unroll
        for (int i = 0; i < 8; i++) {
            float2 p = unpack2(acc[i]);
            reinterpret_cast<float2*>(hv)[i] = make_float2(silu_f(p.x), silu_f(p.y));
        }
        float4* hrow = reinterpret_cast<float4*>(&s_h[tid][0]);
#pragma unroll
        for (int i = 0; i < 4; i++) hrow[i] = hv[i];
    }
    __syncthreads();

    unsigned long long acc2[8];
    {
        float b = b2[tid];
        unsigned long long bbp = pack2(b, b);
#pragma unroll
        for (int i = 0; i < 8; i++) acc2[i] = bbp;
    }
    const float* w2p = W2 + tid;
#pragma unroll 4
    for (int k = 0; k < H; k++) {
        float w = w2p[(size_t)k * H];
        fma16_row(acc2, pack2(w, w), &s_h[k][0]);
    }

    float vals[NT], sum[NT], sq[NT];
#pragma unroll
    for (int i = 0; i < 8; i++) {
        float2 p = unpack2(acc2[i]);
        vals[2 * i] = p.x; vals[2 * i + 1] = p.y;
    }
#pragma unroll
    for (int e = 0; e < NT; e++) { sum[e] = vals[e]; sq[e] = vals[e] * vals[e]; }
#pragma unroll
    for (int off = 16; off > 0; off >>= 1) {
#pragma unroll
        for (int e = 0; e < NT; e++) {
            sum[e] += __shfl_xor_sync(0xffffffffu, sum[e], off);
            sq[e]  += __shfl_xor_sync(0xffffffffu, sq[e],  off);
        }
    }
    const int warp = tid >> 5;
    if ((tid & 31) == 0) {
#pragma unroll
        for (int e = 0; e < NT; e++) { s_red[0][e][warp] = sum[e]; s_red[1][e][warp] = sq[e]; }
    }
    __syncthreads();

    const float gj = gg[tid], bj = bb[tid];
#pragma unroll
    for (int e = 0; e < NT; e++) {
        float s   = s_red[0][e][0] + s_red[0][e][1] + s_red[0][e][2] + s_red[0][e][3];
        float ss  = s_red[1][e][0] + s_red[1][e][1] + s_red[1][e][2] + s_red[1][e][3];
        float mu  = s * (1.0f / H);
        float var = fmaxf(ss * (1.0f / H) - mu * mu, 0.0f);
        float inv = rsqrtf(var + EPSV);
        float out = s_cat[H + tid][e] + (vals[e] - mu) * inv * gj + bj; // residual
        nfio[(size_t)(n0 + e) * H + tid] = out;
    }
}

extern "C" void kernel_launch(void* const* d_in, const int* in_sizes, int n_in,
                              void* d_out, int out_size)
{
    const float* efeat = (const float*)d_in[0];
    const float* nfeat = (const float*)d_in[1];
    const int*   src   = (const int*)  d_in[2];
    const int*   dst   = (const int*)  d_in[3];
    const float* eW1   = (const float*)d_in[4];
    const float* eb1   = (const float*)d_in[5];
    const float* eW2   = (const float*)d_in[6];
    const float* eb2   = (const float*)d_in[7];
    const float* eg    = (const float*)d_in[8];
    const float* ebt   = (const float*)d_in[9];
    const float* nW1   = (const float*)d_in[10];
    const float* nb1   = (const float*)d_in[11];
    const float* nW2   = (const float*)d_in[12];
    const float* nb2   = (const float*)d_in[13];
    const float* ng    = (const float*)d_in[14];
    const float* nbt   = (const float*)d_in[15];

    const int E = in_sizes[0] / H;   // 160000
    const int N = in_sizes[1] / H;   // 10000

    // Output layout: ef [E*H] then nf [N*H]; operate in place on d_out.
    float* ef = (float*)d_out;
    float* nf = ef + (size_t)E * H;

    cudaMemcpyAsync(ef, efeat, sizeof(float) * (size_t)E * H, cudaMemcpyDeviceToDevice);
    cudaMemcpyAsync(nf, nfeat, sizeof(float) * (size_t)N * H, cudaMemcpyDeviceToDevice);

    const int aggTotal = N * H;
    for (int l = 0; l < LAYERS; l++) {
        zero_agg_kernel<<<(aggTotal + 255) / 256, 256>>>(aggTotal);
        edge_kernel<<<E / ET, 128>>>(
            ef, nf, src, dst,
            eW1 + (size_t)l * 3 * H * H, eb1 + (size_t)l * H,
            eW2 + (size_t)l * H * H,     eb2 + (size_t)l * H,
            eg  + (size_t)l * H,         ebt + (size_t)l * H);
        node_kernel<<<N / NT, 128>>>(
            nf,
            nW1 + (size_t)l * 2 * H * H, nb1 + (size_t)l * H,
            nW2 + (size_t)l * H * H,     nb2 + (size_t)l * H,
            ng  + (size_t)l * H,         nbt + (size_t)l * H);
    }
}

// round 17
// speedup vs baseline: 1.3584x; 1.2274x over previous
#include <cuda_runtime.h>
#include <math.h>

// Problem constants (fixed: N_NODES=10000, N_EDGES=160000, H=128, L=16)
#define H      128
#define NMAX   10000
#define LAYERS 16
#define EPSV   1e-5f
#define ET     16   // edges per block (edge kernel)
#define NT     16   // nodes per block (node kernel)
#define PADR   20   // padded shared row (floats): 80B, 16B-aligned, 4-way-conflict stores

// Scratch: scatter-sum accumulator. Zero-initialized at module load; node_kernel
// re-zeroes after consuming, so it is zero at entry of every kernel_launch/replay.
__device__ float g_agg[(size_t)NMAX * H];

typedef unsigned long long ull;

// ---- packed f32x2 helpers (FFMA2 — 2x fp32 FMA throughput on sm_103a) ----
__device__ __forceinline__ void ffma2(ull& d, ull a, ull b) {
    asm("fma.rn.f32x2 %0, %1, %2, %0;" : "+l"(d) : "l"(a), "l"(b));
}
__device__ __forceinline__ ull pack2(float x, float y) {
    ull r;
    asm("mov.b64 %0, {%1, %2};" : "=l"(r) : "f"(x), "f"(y));
    return r;
}
__device__ __forceinline__ float2 unpack2(ull v) {
    float2 r;
    asm("mov.b64 {%0, %1}, %2;" : "=f"(r.x), "=f"(r.y) : "l"(v));
    return r;
}

__device__ __forceinline__ float silu_f(float x) {
    return x / (1.0f + __expf(-x));
}

// ---------------------------------------------------------------------------
// init copy: d_out[0:E*H] = efeat, d_out[E*H:] = nfeat (float4 vectorized)
// ---------------------------------------------------------------------------
__global__ void copy_init_kernel(const float4* __restrict__ efs,
                                 const float4* __restrict__ nfs,
                                 float4* __restrict__ dst,
                                 int n_ef4, int n_tot4) {
    int i = blockIdx.x * blockDim.x + threadIdx.x;
    if (i < n_ef4)       dst[i] = efs[i];
    else if (i < n_tot4) dst[i] = nfs[i - n_ef4];
}

// ---------------------------------------------------------------------------
// Edge update: cat=[ef, nf[src], nf[dst]] (3H) -> Lin+SiLU -> Lin -> LN -> +ef
// Also scatter-adds into g_agg[dst].
// Block = 16 edges, 64 threads. Thread owns output columns (2t, 2t+1):
// one LDG.64 of weights feeds 16 FFMA2 per 4 broadcast LDS.128 (FMA:LDS = 4:1).
// ---------------------------------------------------------------------------
__global__ __launch_bounds__(64) void edge_kernel(
    float* __restrict__ ef, const float* __restrict__ nf,
    const int* __restrict__ src, const int* __restrict__ dst,
    const float* __restrict__ W1, const float* __restrict__ b1,   // W1: [3H][H]
    const float* __restrict__ W2, const float* __restrict__ b2,   // W2: [H][H]
    const float* __restrict__ gg, const float* __restrict__ bb)
{
    __shared__ __align__(16) float s_cat[3 * H][PADR]; // transposed: [k][edge]
    __shared__ __align__(16) float s_h[H][PADR];
    __shared__ float s_red[2][2][ET];

    const int tid = threadIdx.x;       // 0..63
    const int j0  = 2 * tid;           // owned column pair
    const int e0  = blockIdx.x * ET;

    // ---- prologue: gather + transpose into smem ----
#pragma unroll
    for (int e = 0; e < ET; e++) {
        int ei = e0 + e;
        int si = __ldg(&src[ei]);
        int di = __ldg(&dst[ei]);
        int c0 = tid, c1 = tid + 64;
        s_cat[c0][e]         = ef[(size_t)ei * H + c0];
        s_cat[c1][e]         = ef[(size_t)ei * H + c1];
        s_cat[H + c0][e]     = nf[(size_t)si * H + c0];
        s_cat[H + c1][e]     = nf[(size_t)si * H + c1];
        s_cat[2 * H + c0][e] = nf[(size_t)di * H + c0];
        s_cat[2 * H + c1][e] = nf[(size_t)di * H + c1];
    }
    __syncthreads();

    // ---- GEMM1 (K=3H) + SiLU ----
    ull a0[8], a1[8];
    {
        float2 b = *reinterpret_cast<const float2*>(&b1[j0]);
        ull p0 = pack2(b.x, b.x), p1 = pack2(b.y, b.y);
#pragma unroll
        for (int i = 0; i < 8; i++) { a0[i] = p0; a1[i] = p1; }
    }
#pragma unroll 4
    for (int k = 0; k < 3 * H; k++) {
        float2 w = __ldg(reinterpret_cast<const float2*>(&W1[(size_t)k * H + j0]));
        ull w0 = pack2(w.x, w.x), w1 = pack2(w.y, w.y);
        const ulonglong2* cp = reinterpret_cast<const ulonglong2*>(&s_cat[k][0]);
        ulonglong2 c0 = cp[0], c1 = cp[1], c2 = cp[2], c3 = cp[3];
        ffma2(a0[0], w0, c0.x); ffma2(a0[1], w0, c0.y);
        ffma2(a0[2], w0, c1.x); ffma2(a0[3], w0, c1.y);
        ffma2(a0[4], w0, c2.x); ffma2(a0[5], w0, c2.y);
        ffma2(a0[6], w0, c3.x); ffma2(a0[7], w0, c3.y);
        ffma2(a1[0], w1, c0.x); ffma2(a1[1], w1, c0.y);
        ffma2(a1[2], w1, c1.x); ffma2(a1[3], w1, c1.y);
        ffma2(a1[4], w1, c2.x); ffma2(a1[5], w1, c2.y);
        ffma2(a1[6], w1, c3.x); ffma2(a1[7], w1, c3.y);
    }
    // SiLU -> s_h rows j0, j0+1 (16 floats each, 4x STS.128)
    {
        float4* r0 = reinterpret_cast<float4*>(&s_h[j0][0]);
        float4* r1 = reinterpret_cast<float4*>(&s_h[j0 + 1][0]);
#pragma unroll
        for (int i = 0; i < 4; i++) {
            float2 x0 = unpack2(a0[2 * i]), x1 = unpack2(a0[2 * i + 1]);
            r0[i] = make_float4(silu_f(x0.x), silu_f(x0.y), silu_f(x1.x), silu_f(x1.y));
            float2 y0 = unpack2(a1[2 * i]), y1 = unpack2(a1[2 * i + 1]);
            r1[i] = make_float4(silu_f(y0.x), silu_f(y0.y), silu_f(y1.x), silu_f(y1.y));
        }
    }
    __syncthreads();

    // ---- GEMM2 (K=H) ----
    {
        float2 b = *reinterpret_cast<const float2*>(&b2[j0]);
        ull p0 = pack2(b.x, b.x), p1 = pack2(b.y, b.y);
#pragma unroll
        for (int i = 0; i < 8; i++) { a0[i] = p0; a1[i] = p1; }
    }
#pragma unroll 4
    for (int k = 0; k < H; k++) {
        float2 w = __ldg(reinterpret_cast<const float2*>(&W2[(size_t)k * H + j0]));
        ull w0 = pack2(w.x, w.x), w1 = pack2(w.y, w.y);
        const ulonglong2* cp = reinterpret_cast<const ulonglong2*>(&s_h[k][0]);
        ulonglong2 c0 = cp[0], c1 = cp[1], c2 = cp[2], c3 = cp[3];
        ffma2(a0[0], w0, c0.x); ffma2(a0[1], w0, c0.y);
        ffma2(a0[2], w0, c1.x); ffma2(a0[3], w0, c1.y);
        ffma2(a0[4], w0, c2.x); ffma2(a0[5], w0, c2.y);
        ffma2(a0[6], w0, c3.x); ffma2(a0[7], w0, c3.y);
        ffma2(a1[0], w1, c0.x); ffma2(a1[1], w1, c0.y);
        ffma2(a1[2], w1, c1.x); ffma2(a1[3], w1, c1.y);
        ffma2(a1[4], w1, c2.x); ffma2(a1[5], w1, c2.y);
        ffma2(a1[6], w1, c3.x); ffma2(a1[7], w1, c3.y);
    }

    // ---- LayerNorm over 128 cols per edge ----
    float v0[ET], v1[ET];
#pragma unroll
    for (int i = 0; i < 8; i++) {
        float2 p = unpack2(a0[i]); v0[2 * i] = p.x; v0[2 * i + 1] = p.y;
        float2 q = unpack2(a1[i]); v1[2 * i] = q.x; v1[2 * i + 1] = q.y;
    }
    float sum[ET], sq[ET];
#pragma unroll
    for (int e = 0; e < ET; e++) {
        sum[e] = v0[e] + v1[e];
        sq[e]  = v0[e] * v0[e] + v1[e] * v1[e];
    }
#pragma unroll
    for (int off = 16; off > 0; off >>= 1) {
#pragma unroll
        for (int e = 0; e < ET; e++) {
            sum[e] += __shfl_xor_sync(0xffffffffu, sum[e], off);
            sq[e]  += __shfl_xor_sync(0xffffffffu, sq[e],  off);
        }
    }
    const int warp = tid >> 5;
    const int lane = tid & 31;
    if (lane < ET) { s_red[0][warp][lane] = sum[lane]; s_red[1][warp][lane] = sq[lane]; }
    __syncthreads();

    const float2 gv = *reinterpret_cast<const float2*>(&gg[j0]);
    const float2 bv = *reinterpret_cast<const float2*>(&bb[j0]);
#pragma unroll
    for (int e = 0; e < ET; e++) {
        float s   = s_red[0][0][e] + s_red[0][1][e];
        float ss  = s_red[1][0][e] + s_red[1][1][e];
        float mu  = s * (1.0f / H);
        float var = fmaxf(ss * (1.0f / H) - mu * mu, 0.0f);
        float inv = rsqrtf(var + EPSV);
        float o0 = s_cat[j0][e]     + (v0[e] - mu) * inv * gv.x + bv.x; // residual
        float o1 = s_cat[j0 + 1][e] + (v1[e] - mu) * inv * gv.y + bv.y;
        int ei = e0 + e;
        int di = __ldg(&dst[ei]);
        *reinterpret_cast<float2*>(&ef[(size_t)ei * H + j0]) = make_float2(o0, o1);
        atomicAdd(&g_agg[(size_t)di * H + j0],     o0);  // segment_sum by dst
        atomicAdd(&g_agg[(size_t)di * H + j0 + 1], o1);
    }
}

// ---------------------------------------------------------------------------
// Node update: cat=[agg, nf] (2H) -> Lin+SiLU -> Lin -> LN -> +nf (in place).
// Consumes g_agg and re-zeroes it for the next layer (and next graph replay).
// ---------------------------------------------------------------------------
__global__ __launch_bounds__(128) void node_kernel(
    float* __restrict__ nfio,
    const float* __restrict__ W1, const float* __restrict__ b1,   // W1: [2H][H]
    const float* __restrict__ W2, const float* __restrict__ b2,   // W2: [H][H]
    const float* __restrict__ gg, const float* __restrict__ bb)
{
    __shared__ __align__(16) float s_cat[2 * H][PADR];
    __shared__ __align__(16) float s_h[H][PADR];
    __shared__ float s_red[2][NT][4];

    const int tid = threadIdx.x;
    const int n0  = blockIdx.x * NT;

#pragma unroll
    for (int e = 0; e < NT; e++) {
        int ni = n0 + e;
        size_t gi = (size_t)ni * H + tid;
        s_cat[tid][e]     = g_agg[gi];
        g_agg[gi]         = 0.0f;          // reset for next layer / replay
        s_cat[H + tid][e] = nfio[gi];
    }
    __syncthreads();

    ull acc[8];
    {
        float b = b1[tid];
        ull bp = pack2(b, b);
#pragma unroll
        for (int i = 0; i < 8; i++) acc[i] = bp;
    }
    const float* w1p = W1 + tid;
#pragma unroll 4
    for (int k = 0; k < 2 * H; k++) {
        float w = w1p[(size_t)k * H];
        ull ww = pack2(w, w);
        const ulonglong2* cp = reinterpret_cast<const ulonglong2*>(&s_cat[k][0]);
        ulonglong2 c0 = cp[0], c1 = cp[1], c2 = cp[2], c3 = cp[3];
        ffma2(acc[0], ww, c0.x); ffma2(acc[1], ww, c0.y);
        ffma2(acc[2], ww, c1.x); ffma2(acc[3], ww, c1.y);
        ffma2(acc[4], ww, c2.x); ffma2(acc[5], ww, c2.y);
        ffma2(acc[6], ww, c3.x); ffma2(acc[7], ww, c3.y);
    }
    {
        float4* hrow = reinterpret_cast<float4*>(&s_h[tid][0]);
#pragma unroll
        for (int i = 0; i < 4; i++) {
            float2 x0 = unpack2(acc[2 * i]), x1 = unpack2(acc[2 * i + 1]);
            hrow[i] = make_float4(silu_f(x0.x), silu_f(x0.y), silu_f(x1.x), silu_f(x1.y));
        }
    }
    __syncthreads();

    ull acc2[8];
    {
        float b = b2[tid];
        ull bp = pack2(b, b);
#pragma unroll
        for (int i = 0; i < 8; i++) acc2[i] = bp;
    }
    const float* w2p = W2 + tid;
#pragma unroll 4
    for (int k = 0; k < H; k++) {
        float w = w2p[(size_t)k * H];
        ull ww = pack2(w, w);
        const ulonglong2* cp = reinterpret_cast<const ulonglong2*>(&s_h[k][0]);
        ulonglong2 c0 = cp[0], c1 = cp[1], c2 = cp[2], c3 = cp[3];
        ffma2(acc2[0], ww, c0.x); ffma2(acc2[1], ww, c0.y);
        ffma2(acc2[2], ww, c1.x); ffma2(acc2[3], ww, c1.y);
        ffma2(acc2[4], ww, c2.x); ffma2(acc2[5], ww, c2.y);
        ffma2(acc2[6], ww, c3.x); ffma2(acc2[7], ww, c3.y);
    }

    float vals[NT], sum[NT], sq[NT];
#pragma unroll
    for (int i = 0; i < 8; i++) {
        float2 p = unpack2(acc2[i]);
        vals[2 * i] = p.x; vals[2 * i + 1] = p.y;
    }
#pragma unroll
    for (int e = 0; e < NT; e++) { sum[e] = vals[e]; sq[e] = vals[e] * vals[e]; }
#pragma unroll
    for (int off = 16; off > 0; off >>= 1) {
#pragma unroll
        for (int e = 0; e < NT; e++) {
            sum[e] += __shfl_xor_sync(0xffffffffu, sum[e], off);
            sq[e]  += __shfl_xor_sync(0xffffffffu, sq[e],  off);
        }
    }
    const int warp = tid >> 5;
    if ((tid & 31) == 0) {
#pragma unroll
        for (int e = 0; e < NT; e++) { s_red[0][e][warp] = sum[e]; s_red[1][e][warp] = sq[e]; }
    }
    __syncthreads();

    const float gj = gg[tid], bj = bb[tid];
#pragma unroll
    for (int e = 0; e < NT; e++) {
        float s   = s_red[0][e][0] + s_red[0][e][1] + s_red[0][e][2] + s_red[0][e][3];
        float ss  = s_red[1][e][0] + s_red[1][e][1] + s_red[1][e][2] + s_red[1][e][3];
        float mu  = s * (1.0f / H);
        float var = fmaxf(ss * (1.0f / H) - mu * mu, 0.0f);
        float inv = rsqrtf(var + EPSV);
        float out = s_cat[H + tid][e] + (vals[e] - mu) * inv * gj + bj; // residual
        nfio[(size_t)(n0 + e) * H + tid] = out;
    }
}

extern "C" void kernel_launch(void* const* d_in, const int* in_sizes, int n_in,
                              void* d_out, int out_size)
{
    const float* efeat = (const float*)d_in[0];
    const float* nfeat = (const float*)d_in[1];
    const int*   src   = (const int*)  d_in[2];
    const int*   dst   = (const int*)  d_in[3];
    const float* eW1   = (const float*)d_in[4];
    const float* eb1   = (const float*)d_in[5];
    const float* eW2   = (const float*)d_in[6];
    const float* eb2   = (const float*)d_in[7];
    const float* eg    = (const float*)d_in[8];
    const float* ebt   = (const float*)d_in[9];
    const float* nW1   = (const float*)d_in[10];
    const float* nb1   = (const float*)d_in[11];
    const float* nW2   = (const float*)d_in[12];
    const float* nb2   = (const float*)d_in[13];
    const float* ng    = (const float*)d_in[14];
    const float* nbt   = (const float*)d_in[15];

    const int E = in_sizes[0] / H;   // 160000
    const int N = in_sizes[1] / H;   // 10000

    // Output layout: ef [E*H] then nf [N*H]; operate in place on d_out.
    float* ef = (float*)d_out;
    float* nf = ef + (size_t)E * H;

    const int n_ef4  = E * H / 4;
    const int n_tot4 = (E + N) * H / 4;
    copy_init_kernel<<<(n_tot4 + 511) / 512, 512>>>(
        (const float4*)efeat, (const float4*)nfeat, (float4*)d_out, n_ef4, n_tot4);

    for (int l = 0; l < LAYERS; l++) {
        edge_kernel<<<E / ET, 64>>>(
            ef, nf, src, dst,
            eW1 + (size_t)l * 3 * H * H, eb1 + (size_t)l * H,
            eW2 + (size_t)l * H * H,     eb2 + (size_t)l * H,
            eg  + (size_t)l * H,         ebt + (size_t)l * H);
        node_kernel<<<N / NT, 128>>>(
            nf,
            nW1 + (size_t)l * 2 * H * H, nb1 + (size_t)l * H,
            nW2 + (size_t)l * H * H,     nb2 + (size_t)l * H,
            ng  + (size_t)l * H,         nbt + (size_t)l * H);
    }
}